// round 5
// baseline (speedup 1.0000x reference)
#include <cuda_runtime.h>
#include <math.h>

// Problem constants (fixed shapes)
#define BATCH 1024
#define HW 49
#define NN (BATCH*HW)        // 50176
#define INDIM 1024
#define HIDD 512
#define EPB 84               // edges per batch: 42 horizontal + 42 vertical
#define EE (BATCH*EPB)       // 86016
#define EDGE_BLOCKS 336      // EE / 256
#define STAT_BLOCKS 512

// Scratch (static device globals; no allocations allowed)
__device__ float g_node[(size_t)NN*INDIM];   // node features; reused as decoder output
__device__ float g_h1  [(size_t)NN*HIDD];
__device__ float g_h2  [(size_t)NN*HIDD];
__device__ float g_coords_part[(size_t)NN*16];
__device__ float g_coords[NN*2];
__device__ float g_ea  [EE];
__device__ float g_alpha[EE];
__device__ float g_nodew[NN];
__device__ float g_epart[EDGE_BLOCKS];
__device__ float g_sumexp[1];
__device__ float g_psum[STAT_BLOCKS*HIDD];
__device__ float g_psq [STAT_BLOCKS*HIDD];
__device__ float g_scale[HIDD];
__device__ float g_shift[HIDD];

__device__ __forceinline__ unsigned f2tf(float f) {
    unsigned u; asm("cvt.rna.tf32.f32 %0, %1;" : "=r"(u) : "f"(f)); return u;
}
__device__ __forceinline__ float4 ld4(const float* p) {
    return *reinterpret_cast<const float4*>(p);
}
__device__ __forceinline__ void bn4(float4& v, const float4 sc, const float4 sh) {
    v.x = fmaxf(fmaf(v.x, sc.x, sh.x), 0.f);
    v.y = fmaxf(fmaf(v.y, sc.y, sh.y), 0.f);
    v.z = fmaxf(fmaf(v.z, sc.z, sh.z), 0.f);
    v.w = fmaxf(fmaf(v.w, sc.w, sh.w), 0.f);
}

// Per-row closed-form aggregation descriptor (grid graph: <=2 incoming edges)
struct GcRow { int nL, nU; float wL, wU; };
__device__ __forceinline__ GcRow make_gcrow(int n, const float* __restrict__ alpha) {
    int b = n / HW, pos = n % HW, r = pos / 7, c = pos % 7;
    GcRow g;
    g.nL = (c > 0) ? n - 1 : n;
    g.nU = (r > 0) ? n - 7 : n;
    float wL = (c > 0) ? alpha[b*EPB + r*6 + (c-1)]       : 0.f;
    float wU = (r > 0) ? alpha[b*EPB + 42 + (r-1)*7 + c]  : 0.f;
    int deg = (c > 0) + (r > 0);
    float inv = 1.f / (float)(deg > 0 ? deg : 1);
    g.wL = wL * inv; g.wU = wU * inv;
    return g;
}

// ---------------------------------------------------------------------------
// K1: NCHW concat -> [N,1024] row-major + per-tile coords partial dots
__global__ void k_build_node(const float* __restrict__ vis,
                             const float* __restrict__ tac,
                             const float* __restrict__ pW,
                             float* __restrict__ node,
                             float* __restrict__ cpart) {
    int b = blockIdx.x >> 3;
    int t = blockIdx.x & 7;
    const float* src = (t < 4) ? vis : tac;
    __shared__ float tile[128*49];
    __shared__ float sW[256];
    const float* p = src + ((size_t)b*512 + (size_t)(t & 3)*128) * 49;
    for (int i = threadIdx.x; i < 128*49; i += 256) tile[i] = p[i];
    if (threadIdx.x < 256) sW[threadIdx.x] = pW[t*256 + threadIdx.x];  // rows t*128.., 2 cols
    __syncthreads();
    for (int i = threadIdx.x; i < 128*49; i += 256) {
        int pos = i >> 7, ch = i & 127;
        node[((size_t)(b*HW + pos))*INDIM + t*128 + ch] = tile[ch*49 + pos];
    }
    if (threadIdx.x < 98) {
        int pos = threadIdx.x >> 1, comp = threadIdx.x & 1;
        float s = 0.f;
        #pragma unroll 8
        for (int ch = 0; ch < 128; ch++)
            s += tile[ch*49 + pos] * sW[ch*2 + comp];
        cpart[((size_t)(b*HW + pos))*16 + t*2 + comp] = s;
    }
}

// Reduce 8 tile-partials -> coords (+ bias)
__global__ void k_coords_fin(const float* __restrict__ cpart,
                             const float* __restrict__ pb,
                             float* __restrict__ coords) {
    int n = blockIdx.x*256 + threadIdx.x;
    const float4* p = reinterpret_cast<const float4*>(cpart + (size_t)n*16);
    float4 a = p[0], b4 = p[1], c4 = p[2], d4 = p[3];
    float c0 = a.x + a.z + b4.x + b4.z + c4.x + c4.z + d4.x + d4.z;
    float c1 = a.y + a.w + b4.y + b4.w + c4.y + c4.w + d4.y + d4.w;
    coords[2*n]   = c0 + pb[0];
    coords[2*n+1] = c1 + pb[1];
}

// ---------------------------------------------------------------------------
// K3: per-edge attr + exp, per-block partial sums (deterministic)
__global__ void k_edge(const float* __restrict__ coords,
                       float* __restrict__ ea,
                       float* __restrict__ ex,
                       float* __restrict__ epart) {
    int e = blockIdx.x*256 + threadIdx.x;
    float v = 0.f;
    {
        int b = e / EPB, k = e % EPB;
        int s, d;
        if (k < 42) { int r = k/6, c = k%6; s = r*7+c; d = s+1; }
        else        { int k2 = k-42; int r = k2/7, c = k2%7; s = r*7+c; d = s+7; }
        s += b*HW; d += b*HW;
        float dx = coords[2*s]   - coords[2*d];
        float dy = coords[2*s+1] - coords[2*d+1];
        float dist = sqrtf(dx*dx + dy*dy);
        float a = 1.f / (1.f + expf(-(1.f/(dist + 1e-6f))));
        ea[e] = a;
        v = expf(a);
        ex[e] = v;
    }
    __shared__ float red[8];
    #pragma unroll
    for (int o = 16; o; o >>= 1) v += __shfl_down_sync(0xffffffffu, v, o);
    if ((threadIdx.x & 31) == 0) red[threadIdx.x >> 5] = v;
    __syncthreads();
    if (threadIdx.x < 8) {
        float s = red[threadIdx.x];
        #pragma unroll
        for (int o = 4; o; o >>= 1) s += __shfl_down_sync(0xffu, s, o);
        if (threadIdx.x == 0) epart[blockIdx.x] = s;
    }
}

__global__ void k_sumexp(const float* __restrict__ epart, float* __restrict__ out) {
    int t = threadIdx.x;
    float v = (t < EDGE_BLOCKS) ? epart[t] : 0.f;
    __shared__ float red[16];
    #pragma unroll
    for (int o = 16; o; o >>= 1) v += __shfl_down_sync(0xffffffffu, v, o);
    if ((t & 31) == 0) red[t >> 5] = v;
    __syncthreads();
    if (t < 16) {
        float s = red[t];
        #pragma unroll
        for (int o = 8; o; o >>= 1) s += __shfl_down_sync(0xffffu, s, o);
        if (t == 0) out[0] = s;
    }
}

__global__ void k_alpha(float* __restrict__ ex, const float* __restrict__ sumexp) {
    int e = blockIdx.x*256 + threadIdx.x;
    float inv = 1.f / (sumexp[0] + 1e-8f);
    ex[e] = ex[e] * inv;
}

__global__ void k_nodew(const float* __restrict__ ea, float* __restrict__ nw) {
    int n = blockIdx.x*256 + threadIdx.x;
    int b = n / HW, pos = n % HW, r = pos / 7, c = pos % 7;
    const float* base = ea + b*EPB;
    float s = 0.f; int cnt = 0;
    if (c > 0) { s += base[r*6 + (c-1)];     cnt++; }
    if (c < 6) { s += base[r*6 + c];         cnt++; }
    if (r > 0) { s += base[42 + (r-1)*7 + c]; cnt++; }
    if (r < 6) { s += base[42 + r*7 + c];     cnt++; }
    nw[n] = s / (float)cnt;
}

// ---------------------------------------------------------------------------
// TF32 tensor-core GEMM with fused graph-conv:
//   C = agg(z) @ Wrel + z @ Wroot + bias,  z = BN? relu(scale*x+shift) : x
// Block: 256 thr (8 warps, 4Mx2N), tile 128x128, BK=16, double-buffered.
struct TileRegs { float4 a0, a1, b0, b1; };

__device__ __forceinline__ void s_store(unsigned (*As)[132], unsigned (*Bs)[132],
                                        int tid, const TileRegs& r) {
    int row = tid >> 2, kq = (tid & 3) << 2;
    As[kq+0][row] = f2tf(r.a0.x); As[kq+1][row] = f2tf(r.a0.y);
    As[kq+2][row] = f2tf(r.a0.z); As[kq+3][row] = f2tf(r.a0.w);
    As[kq+0][row+64] = f2tf(r.a1.x); As[kq+1][row+64] = f2tf(r.a1.y);
    As[kq+2][row+64] = f2tf(r.a1.z); As[kq+3][row+64] = f2tf(r.a1.w);
    int kr = tid >> 5, nq = (tid & 31) << 2;
    uint4 p0 = make_uint4(f2tf(r.b0.x), f2tf(r.b0.y), f2tf(r.b0.z), f2tf(r.b0.w));
    uint4 p1 = make_uint4(f2tf(r.b1.x), f2tf(r.b1.y), f2tf(r.b1.z), f2tf(r.b1.w));
    *reinterpret_cast<uint4*>(&Bs[kr][nq])   = p0;
    *reinterpret_cast<uint4*>(&Bs[kr+8][nq]) = p1;
}

#define MMA_TF32(d, a, b0v, b1v) \
    asm volatile("mma.sync.aligned.m16n8k8.row.col.f32.tf32.tf32.f32 " \
                 "{%0,%1,%2,%3}, {%4,%5,%6,%7}, {%8,%9}, {%0,%1,%2,%3};" \
                 : "+f"(d[0]), "+f"(d[1]), "+f"(d[2]), "+f"(d[3]) \
                 : "r"(a[0]), "r"(a[1]), "r"(a[2]), "r"(a[3]), "r"(b0v), "r"(b1v))

__device__ __forceinline__ void mma_tile(const unsigned (*As)[132], const unsigned (*Bs)[132],
                                         int wm, int wn, int lane, float acc[2][8][4]) {
    int grp = lane >> 2, tig = lane & 3;
    #pragma unroll
    for (int ks = 0; ks < 16; ks += 8) {
        unsigned ua[2][4];
        #pragma unroll
        for (int mt = 0; mt < 2; mt++) {
            int m = (wm << 5) + (mt << 4) + grp;
            ua[mt][0] = As[ks + tig][m];
            ua[mt][1] = As[ks + tig][m + 8];
            ua[mt][2] = As[ks + tig + 4][m];
            ua[mt][3] = As[ks + tig + 4][m + 8];
        }
        #pragma unroll
        for (int nt = 0; nt < 8; nt++) {
            int n = (wn << 6) + (nt << 3) + grp;
            unsigned b0 = Bs[ks + tig][n];
            unsigned b1 = Bs[ks + tig + 4][n];
            MMA_TF32(acc[0][nt], ua[0], b0, b1);
            MMA_TF32(acc[1][nt], ua[1], b0, b1);
        }
    }
}

template<bool BN>
__global__ __launch_bounds__(256)
void k_gemm_gc(const float* __restrict__ x, const float* __restrict__ Wrel,
               const float* __restrict__ Wroot, const float* __restrict__ alpha,
               const float* __restrict__ bias, const float* __restrict__ scale,
               const float* __restrict__ shift, float* __restrict__ C, int Kd) {
    __shared__ __align__(16) unsigned As[2][16][132];
    __shared__ __align__(16) unsigned Bs[2][16][132];
    int tid = threadIdx.x, lane = tid & 31, wid = tid >> 5;
    int wm = wid & 3, wn = wid >> 2;
    int rowBase = blockIdx.y * 128, colBase = blockIdx.x * 128;
    int row = tid >> 2, kq = (tid & 3) << 2;
    int kr = tid >> 5, nq = (tid & 31) << 2;
    int nA = rowBase + row, nB = nA + 64;
    GcRow gA = make_gcrow(nA, alpha), gB = make_gcrow(nB, alpha);
    int nHalf = Kd >> 4, niter = nHalf * 2;

    float acc[2][8][4];
    #pragma unroll
    for (int mt = 0; mt < 2; mt++)
        #pragma unroll
        for (int nt = 0; nt < 8; nt++)
            #pragma unroll
            for (int i = 0; i < 4; i++) acc[mt][nt][i] = 0.f;

    auto do_load = [&](int iter, TileRegs& r) {
        int pass = iter >= nHalf;
        int kk = (iter - (pass ? nHalf : 0)) << 4;
        const float* W = pass ? Wroot : Wrel;
        r.b0 = ld4(W + (size_t)(kk + kr)*HIDD + colBase + nq);
        r.b1 = ld4(W + (size_t)(kk + kr + 8)*HIDD + colBase + nq);
        float4 sc, sh;
        if (BN) { sc = ld4(scale + kk + kq); sh = ld4(shift + kk + kq); }
        if (pass) {
            float4 v0 = ld4(x + (size_t)nA*Kd + kk + kq);
            float4 v1 = ld4(x + (size_t)nB*Kd + kk + kq);
            if (BN) { bn4(v0, sc, sh); bn4(v1, sc, sh); }
            r.a0 = v0; r.a1 = v1;
        } else {
            float4 l0 = ld4(x + (size_t)gA.nL*Kd + kk + kq);
            float4 u0 = ld4(x + (size_t)gA.nU*Kd + kk + kq);
            float4 l1 = ld4(x + (size_t)gB.nL*Kd + kk + kq);
            float4 u1 = ld4(x + (size_t)gB.nU*Kd + kk + kq);
            if (BN) { bn4(l0, sc, sh); bn4(u0, sc, sh); bn4(l1, sc, sh); bn4(u1, sc, sh); }
            r.a0 = make_float4(gA.wL*l0.x + gA.wU*u0.x, gA.wL*l0.y + gA.wU*u0.y,
                               gA.wL*l0.z + gA.wU*u0.z, gA.wL*l0.w + gA.wU*u0.w);
            r.a1 = make_float4(gB.wL*l1.x + gB.wU*u1.x, gB.wL*l1.y + gB.wU*u1.y,
                               gB.wL*l1.z + gB.wU*u1.z, gB.wL*l1.w + gB.wU*u1.w);
        }
    };

    TileRegs r;
    do_load(0, r);
    s_store(As[0], Bs[0], tid, r);
    __syncthreads();

    int buf = 0;
    for (int iter = 0; iter < niter; ++iter) {
        if (iter + 1 < niter) do_load(iter + 1, r);
        mma_tile(As[buf], Bs[buf], wm, wn, lane, acc);
        if (iter + 1 < niter) {
            s_store(As[buf ^ 1], Bs[buf ^ 1], tid, r);
            __syncthreads();
            buf ^= 1;
        }
    }

    int grp = lane >> 2, tig = lane & 3;
    #pragma unroll
    for (int mt = 0; mt < 2; mt++) {
        #pragma unroll
        for (int nt = 0; nt < 8; nt++) {
            int orow = rowBase + (wm << 5) + (mt << 4) + grp;
            int col = colBase + (wn << 6) + (nt << 3) + (tig << 1);
            float2 lo = make_float2(acc[mt][nt][0] + bias[col], acc[mt][nt][1] + bias[col+1]);
            float2 hi = make_float2(acc[mt][nt][2] + bias[col], acc[mt][nt][3] + bias[col+1]);
            *reinterpret_cast<float2*>(C + (size_t)orow*HIDD + col)     = lo;
            *reinterpret_cast<float2*>(C + (size_t)(orow+8)*HIDD + col) = hi;
        }
    }
}

// Decoder GEMM: Y = relu( z@W[0:512] + nodew*W[512] + bias ),  z = relu(scale*x+shift)
__global__ __launch_bounds__(256)
void k_gemm_dec_tf32(const float* __restrict__ x, const float* __restrict__ W,
                     const float* __restrict__ nodew, const float* __restrict__ bias,
                     const float* __restrict__ scale, const float* __restrict__ shift,
                     float* __restrict__ Y) {
    const int Kd = HIDD;
    __shared__ __align__(16) unsigned As[2][16][132];
    __shared__ __align__(16) unsigned Bs[2][16][132];
    int tid = threadIdx.x, lane = tid & 31, wid = tid >> 5;
    int wm = wid & 3, wn = wid >> 2;
    int rowBase = blockIdx.y * 128, colBase = blockIdx.x * 128;
    int row = tid >> 2, kq = (tid & 3) << 2;
    int kr = tid >> 5, nq = (tid & 31) << 2;
    int nA = rowBase + row, nB = nA + 64;
    int niter = Kd >> 4;

    float acc[2][8][4];
    #pragma unroll
    for (int mt = 0; mt < 2; mt++)
        #pragma unroll
        for (int nt = 0; nt < 8; nt++)
            #pragma unroll
            for (int i = 0; i < 4; i++) acc[mt][nt][i] = 0.f;

    auto do_load = [&](int iter, TileRegs& r) {
        int kk = iter << 4;
        r.b0 = ld4(W + (size_t)(kk + kr)*HIDD + colBase + nq);
        r.b1 = ld4(W + (size_t)(kk + kr + 8)*HIDD + colBase + nq);
        float4 sc = ld4(scale + kk + kq), sh = ld4(shift + kk + kq);
        float4 v0 = ld4(x + (size_t)nA*Kd + kk + kq);
        float4 v1 = ld4(x + (size_t)nB*Kd + kk + kq);
        bn4(v0, sc, sh); bn4(v1, sc, sh);
        r.a0 = v0; r.a1 = v1;
    };

    TileRegs r;
    do_load(0, r);
    s_store(As[0], Bs[0], tid, r);
    __syncthreads();

    int buf = 0;
    for (int iter = 0; iter < niter; ++iter) {
        if (iter + 1 < niter) do_load(iter + 1, r);
        mma_tile(As[buf], Bs[buf], wm, wn, lane, acc);
        if (iter + 1 < niter) {
            s_store(As[buf ^ 1], Bs[buf ^ 1], tid, r);
            __syncthreads();
            buf ^= 1;
        }
    }

    const float* wlast = W + (size_t)HIDD * HIDD;
    int grp = lane >> 2, tig = lane & 3;
    #pragma unroll
    for (int mt = 0; mt < 2; mt++) {
        #pragma unroll
        for (int nt = 0; nt < 8; nt++) {
            int orow = rowBase + (wm << 5) + (mt << 4) + grp;
            int col = colBase + (wn << 6) + (nt << 3) + (tig << 1);
            float nw0 = nodew[orow], nw1 = nodew[orow + 8];
            float w0 = wlast[col], w1 = wlast[col+1];
            float b0 = bias[col], b1 = bias[col+1];
            float2 lo = make_float2(fmaxf(acc[mt][nt][0] + nw0*w0 + b0, 0.f),
                                    fmaxf(acc[mt][nt][1] + nw0*w1 + b1, 0.f));
            float2 hi = make_float2(fmaxf(acc[mt][nt][2] + nw1*w0 + b0, 0.f),
                                    fmaxf(acc[mt][nt][3] + nw1*w1 + b1, 0.f));
            *reinterpret_cast<float2*>(Y + (size_t)orow*HIDD + col)     = lo;
            *reinterpret_cast<float2*>(Y + (size_t)(orow+8)*HIDD + col) = hi;
        }
    }
}

// ---------------------------------------------------------------------------
// BN stats: deterministic two-stage column sum/sumsq
__global__ void k_colstat(const float* __restrict__ h,
                          float* __restrict__ psum, float* __restrict__ psq) {
    int t = threadIdx.x;
    int blk = blockIdx.x;
    const int rows = NN / STAT_BLOCKS;
    int r0 = blk * rows;
    float s0 = 0.f, q0 = 0.f, s1 = 0.f, q1 = 0.f;
    for (int r = r0; r < r0 + rows; ++r) {
        float v0 = h[(size_t)r*HIDD + t];
        float v1 = h[(size_t)r*HIDD + 256 + t];
        s0 += v0; q0 += v0*v0; s1 += v1; q1 += v1*v1;
    }
    psum[blk*HIDD + t] = s0; psum[blk*HIDD + 256 + t] = s1;
    psq [blk*HIDD + t] = q0; psq [blk*HIDD + 256 + t] = q1;
}

__global__ void k_colfinish(const float* __restrict__ psum, const float* __restrict__ psq,
                            const float* __restrict__ gamma, const float* __restrict__ beta,
                            float* __restrict__ scale, float* __restrict__ shift) {
    int c = threadIdx.x;
    float s = 0.f, q = 0.f;
    for (int j = 0; j < STAT_BLOCKS; j++) { s += psum[j*HIDD + c]; q += psq[j*HIDD + c]; }
    float mean = s / (float)NN;
    float var  = q / (float)NN - mean*mean;
    float sc = gamma[c] * rsqrtf(var + 1e-5f);
    scale[c] = sc;
    shift[c] = beta[c] - mean*sc;
}

// ---------------------------------------------------------------------------
// Output transpose: y[N,512] -> out[B,512,7,7]
__global__ void k_out(const float* __restrict__ y, float* __restrict__ out) {
    int b = blockIdx.x >> 2;
    int t = blockIdx.x & 3;
    __shared__ float tile[49*129];
    for (int i = threadIdx.x; i < 49*128; i += 256) {
        int pos = i >> 7, ch = i & 127;
        tile[pos*129 + ch] = y[((size_t)(b*HW + pos))*HIDD + t*128 + ch];
    }
    __syncthreads();
    for (int i = threadIdx.x; i < 49*128; i += 256) {
        int ch = i / 49, pos = i % 49;
        out[((size_t)(b*512) + t*128 + ch)*HW + pos] = tile[pos*129 + ch];
    }
}

// ---------------------------------------------------------------------------
extern "C" void kernel_launch(void* const* d_in, const int* in_sizes, int n_in,
                              void* d_out, int out_size) {
    const float* vis     = (const float*)d_in[0];
    const float* tac     = (const float*)d_in[1];
    const float* projW   = (const float*)d_in[2];
    const float* projb   = (const float*)d_in[3];
    const float* g1relW  = (const float*)d_in[4];
    const float* g1relb  = (const float*)d_in[5];
    const float* g1rootW = (const float*)d_in[6];
    const float* bn1g    = (const float*)d_in[7];
    const float* bn1b    = (const float*)d_in[8];
    const float* g2relW  = (const float*)d_in[9];
    const float* g2relb  = (const float*)d_in[10];
    const float* g2rootW = (const float*)d_in[11];
    const float* bn2g    = (const float*)d_in[12];
    const float* bn2b    = (const float*)d_in[13];
    const float* decW    = (const float*)d_in[14];
    const float* decb    = (const float*)d_in[15];
    float* out = (float*)d_out;

    float *node, *h1, *h2, *cpart, *coords, *ea, *alpha, *nodew, *epart, *sumexp;
    float *psum, *psq, *scale, *shift;
    cudaGetSymbolAddress((void**)&node,   g_node);
    cudaGetSymbolAddress((void**)&h1,     g_h1);
    cudaGetSymbolAddress((void**)&h2,     g_h2);
    cudaGetSymbolAddress((void**)&cpart,  g_coords_part);
    cudaGetSymbolAddress((void**)&coords, g_coords);
    cudaGetSymbolAddress((void**)&ea,     g_ea);
    cudaGetSymbolAddress((void**)&alpha,  g_alpha);
    cudaGetSymbolAddress((void**)&nodew,  g_nodew);
    cudaGetSymbolAddress((void**)&epart,  g_epart);
    cudaGetSymbolAddress((void**)&sumexp, g_sumexp);
    cudaGetSymbolAddress((void**)&psum,   g_psum);
    cudaGetSymbolAddress((void**)&psq,    g_psq);
    cudaGetSymbolAddress((void**)&scale,  g_scale);
    cudaGetSymbolAddress((void**)&shift,  g_shift);

    dim3 gg(HIDD/128, NN/128);  // (4, 392)

    k_build_node<<<BATCH*8, 256>>>(vis, tac, projW, node, cpart);
    k_coords_fin<<<NN/256, 256>>>(cpart, projb, coords);
    k_edge<<<EDGE_BLOCKS, 256>>>(coords, ea, alpha, epart);
    k_sumexp<<<1, 512>>>(epart, sumexp);
    k_alpha<<<EDGE_BLOCKS, 256>>>(alpha, sumexp);
    k_nodew<<<NN/256, 256>>>(ea, nodew);

    // GC1: fused agg+GEMM (no BN on input)
    k_gemm_gc<false><<<gg, 256>>>(node, g1relW, g1rootW, alpha, g1relb,
                                  nullptr, nullptr, h1, INDIM);
    k_colstat<<<STAT_BLOCKS, 256>>>(h1, psum, psq);
    k_colfinish<<<1, 512>>>(psum, psq, bn1g, bn1b, scale, shift);

    // GC2: fused BN(h1)+relu+agg+GEMM
    k_gemm_gc<true><<<gg, 256>>>(h1, g2relW, g2rootW, alpha, g2relb,
                                 scale, shift, h2, HIDD);
    k_colstat<<<STAT_BLOCKS, 256>>>(h2, psum, psq);
    k_colfinish<<<1, 512>>>(psum, psq, bn2g, bn2b, scale, shift);

    // Decoder: fused BN(h2)+relu + GEMM + rank-1 node_w term -> reuse g_node
    k_gemm_dec_tf32<<<gg, 256>>>(h2, decW, nodew, decb, scale, shift, node);
    k_out<<<BATCH*4, 256>>>(node, out);
}

// round 6
// speedup vs baseline: 1.5624x; 1.5624x over previous
#include <cuda_runtime.h>
#include <math.h>

// Problem constants (fixed shapes)
#define BATCH 1024
#define HW 49
#define NN (BATCH*HW)        // 50176
#define INDIM 1024
#define HIDD 512
#define EPB 84               // edges per batch: 42 horizontal + 42 vertical
#define EE (BATCH*EPB)       // 86016
#define EDGE_BLOCKS 336      // EE / 256
#define STAT_BLOCKS 512

// Scratch (static device globals; no allocations allowed)
__device__ float g_node[(size_t)NN*INDIM];   // node features; reused as decoder output
__device__ float g_P   [(size_t)NN*INDIM];   // cat-GEMM output [N, 1024] = [rel | root]
__device__ float g_h1  [(size_t)NN*HIDD];
__device__ float g_h2  [(size_t)NN*HIDD];
__device__ float g_coords_part[(size_t)NN*16];
__device__ float g_coords[NN*2];
__device__ float g_ea  [EE];
__device__ float g_alpha[EE];
__device__ float g_nodew[NN];
__device__ float g_epart[EDGE_BLOCKS];
__device__ float g_sumexp[1];
__device__ float g_psum[STAT_BLOCKS*HIDD];
__device__ float g_psq [STAT_BLOCKS*HIDD];
__device__ float g_scale[HIDD];
__device__ float g_shift[HIDD];

__device__ __forceinline__ unsigned f2tf(float f) {
    unsigned u; asm("cvt.rna.tf32.f32 %0, %1;" : "=r"(u) : "f"(f)); return u;
}
__device__ __forceinline__ float4 ld4(const float* p) {
    return *reinterpret_cast<const float4*>(p);
}

// ---------------------------------------------------------------------------
// K1: NCHW concat -> [N,1024] row-major + per-tile coords partial dots
__global__ void k_build_node(const float* __restrict__ vis,
                             const float* __restrict__ tac,
                             const float* __restrict__ pW,
                             float* __restrict__ node,
                             float* __restrict__ cpart) {
    int b = blockIdx.x >> 3;
    int t = blockIdx.x & 7;
    const float* src = (t < 4) ? vis : tac;
    __shared__ float tile[128*49];
    __shared__ float sW[256];
    const float* p = src + ((size_t)b*512 + (size_t)(t & 3)*128) * 49;
    for (int i = threadIdx.x; i < 128*49; i += 256) tile[i] = p[i];
    if (threadIdx.x < 256) sW[threadIdx.x] = pW[t*256 + threadIdx.x];
    __syncthreads();
    for (int i = threadIdx.x; i < 128*49; i += 256) {
        int pos = i >> 7, ch = i & 127;
        node[((size_t)(b*HW + pos))*INDIM + t*128 + ch] = tile[ch*49 + pos];
    }
    if (threadIdx.x < 98) {
        int pos = threadIdx.x >> 1, comp = threadIdx.x & 1;
        float s = 0.f;
        #pragma unroll 8
        for (int ch = 0; ch < 128; ch++)
            s += tile[ch*49 + pos] * sW[ch*2 + comp];
        cpart[((size_t)(b*HW + pos))*16 + t*2 + comp] = s;
    }
}

__global__ void k_coords_fin(const float* __restrict__ cpart,
                             const float* __restrict__ pb,
                             float* __restrict__ coords) {
    int n = blockIdx.x*256 + threadIdx.x;
    const float4* p = reinterpret_cast<const float4*>(cpart + (size_t)n*16);
    float4 a = p[0], b4 = p[1], c4 = p[2], d4 = p[3];
    float c0 = a.x + a.z + b4.x + b4.z + c4.x + c4.z + d4.x + d4.z;
    float c1 = a.y + a.w + b4.y + b4.w + c4.y + c4.w + d4.y + d4.w;
    coords[2*n]   = c0 + pb[0];
    coords[2*n+1] = c1 + pb[1];
}

// ---------------------------------------------------------------------------
// K3: per-edge attr + exp, per-block partial sums (deterministic)
__global__ void k_edge(const float* __restrict__ coords,
                       float* __restrict__ ea,
                       float* __restrict__ ex,
                       float* __restrict__ epart) {
    int e = blockIdx.x*256 + threadIdx.x;
    float v = 0.f;
    {
        int b = e / EPB, k = e % EPB;
        int s, d;
        if (k < 42) { int r = k/6, c = k%6; s = r*7+c; d = s+1; }
        else        { int k2 = k-42; int r = k2/7, c = k2%7; s = r*7+c; d = s+7; }
        s += b*HW; d += b*HW;
        float dx = coords[2*s]   - coords[2*d];
        float dy = coords[2*s+1] - coords[2*d+1];
        float dist = sqrtf(dx*dx + dy*dy);
        float a = 1.f / (1.f + expf(-(1.f/(dist + 1e-6f))));
        ea[e] = a;
        v = expf(a);
        ex[e] = v;
    }
    __shared__ float red[8];
    #pragma unroll
    for (int o = 16; o; o >>= 1) v += __shfl_down_sync(0xffffffffu, v, o);
    if ((threadIdx.x & 31) == 0) red[threadIdx.x >> 5] = v;
    __syncthreads();
    if (threadIdx.x < 8) {
        float s = red[threadIdx.x];
        #pragma unroll
        for (int o = 4; o; o >>= 1) s += __shfl_down_sync(0xffu, s, o);
        if (threadIdx.x == 0) epart[blockIdx.x] = s;
    }
}

__global__ void k_sumexp(const float* __restrict__ epart, float* __restrict__ out) {
    int t = threadIdx.x;
    float v = (t < EDGE_BLOCKS) ? epart[t] : 0.f;
    __shared__ float red[16];
    #pragma unroll
    for (int o = 16; o; o >>= 1) v += __shfl_down_sync(0xffffffffu, v, o);
    if ((t & 31) == 0) red[t >> 5] = v;
    __syncthreads();
    if (t < 16) {
        float s = red[t];
        #pragma unroll
        for (int o = 8; o; o >>= 1) s += __shfl_down_sync(0xffffu, s, o);
        if (t == 0) out[0] = s;
    }
}

__global__ void k_alpha(float* __restrict__ ex, const float* __restrict__ sumexp) {
    int e = blockIdx.x*256 + threadIdx.x;
    float inv = 1.f / (sumexp[0] + 1e-8f);
    ex[e] = ex[e] * inv;
}

__global__ void k_nodew(const float* __restrict__ ea, float* __restrict__ nw) {
    int n = blockIdx.x*256 + threadIdx.x;
    int b = n / HW, pos = n % HW, r = pos / 7, c = pos % 7;
    const float* base = ea + b*EPB;
    float s = 0.f; int cnt = 0;
    if (c > 0) { s += base[r*6 + (c-1)];     cnt++; }
    if (c < 6) { s += base[r*6 + c];         cnt++; }
    if (r > 0) { s += base[42 + (r-1)*7 + c]; cnt++; }
    if (r < 6) { s += base[42 + r*7 + c];     cnt++; }
    nw[n] = s / (float)cnt;
}

// ---------------------------------------------------------------------------
// TF32 mma core (proven in R3): 128x128 tile, BK=16, double-buffered,
// 8 warps 4Mx2N, each warp 32x64 via 2x8 m16n8k8. fp32 accum.
struct TileRegs { float4 a0, a1, b0, b1; };

__device__ __forceinline__ void s_store(unsigned (*As)[132], unsigned (*Bs)[132],
                                        int tid, const TileRegs& r) {
    int row = tid >> 2, kq = (tid & 3) << 2;
    As[kq+0][row] = f2tf(r.a0.x); As[kq+1][row] = f2tf(r.a0.y);
    As[kq+2][row] = f2tf(r.a0.z); As[kq+3][row] = f2tf(r.a0.w);
    As[kq+0][row+64] = f2tf(r.a1.x); As[kq+1][row+64] = f2tf(r.a1.y);
    As[kq+2][row+64] = f2tf(r.a1.z); As[kq+3][row+64] = f2tf(r.a1.w);
    int kr = tid >> 5, nq = (tid & 31) << 2;
    uint4 p0 = make_uint4(f2tf(r.b0.x), f2tf(r.b0.y), f2tf(r.b0.z), f2tf(r.b0.w));
    uint4 p1 = make_uint4(f2tf(r.b1.x), f2tf(r.b1.y), f2tf(r.b1.z), f2tf(r.b1.w));
    *reinterpret_cast<uint4*>(&Bs[kr][nq])   = p0;
    *reinterpret_cast<uint4*>(&Bs[kr+8][nq]) = p1;
}

#define MMA_TF32(d, a, b0v, b1v) \
    asm volatile("mma.sync.aligned.m16n8k8.row.col.f32.tf32.tf32.f32 " \
                 "{%0,%1,%2,%3}, {%4,%5,%6,%7}, {%8,%9}, {%0,%1,%2,%3};" \
                 : "+f"(d[0]), "+f"(d[1]), "+f"(d[2]), "+f"(d[3]) \
                 : "r"(a[0]), "r"(a[1]), "r"(a[2]), "r"(a[3]), "r"(b0v), "r"(b1v))

__device__ __forceinline__ void mma_tile(const unsigned (*As)[132], const unsigned (*Bs)[132],
                                         int wm, int wn, int lane, float acc[2][8][4]) {
    int grp = lane >> 2, tig = lane & 3;
    #pragma unroll
    for (int ks = 0; ks < 16; ks += 8) {
        unsigned ua[2][4];
        #pragma unroll
        for (int mt = 0; mt < 2; mt++) {
            int m = (wm << 5) + (mt << 4) + grp;
            ua[mt][0] = As[ks + tig][m];
            ua[mt][1] = As[ks + tig][m + 8];
            ua[mt][2] = As[ks + tig + 4][m];
            ua[mt][3] = As[ks + tig + 4][m + 8];
        }
        #pragma unroll
        for (int nt = 0; nt < 8; nt++) {
            int n = (wn << 6) + (nt << 3) + grp;
            unsigned b0 = Bs[ks + tig][n];
            unsigned b1 = Bs[ks + tig + 4][n];
            MMA_TF32(acc[0][nt], ua[0], b0, b1);
            MMA_TF32(acc[1][nt], ua[1], b0, b1);
        }
    }
}

// Concatenated GEMM: P[:, 0:512] = A @ W0, P[:, 512:1024] = A @ W1.
// Grid (8, NN/128); bx<4 -> W0, else W1. A is ONE coalesced stream.
__global__ __launch_bounds__(256)
void k_gemm_cat(const float* __restrict__ A, const float* __restrict__ W0,
                const float* __restrict__ W1, float* __restrict__ P, int Kd) {
    __shared__ __align__(16) unsigned As[2][16][132];
    __shared__ __align__(16) unsigned Bs[2][16][132];
    int tid = threadIdx.x, lane = tid & 31, wid = tid >> 5;
    int wm = wid & 3, wn = wid >> 2;
    int bx = blockIdx.x;
    const float* W = (bx < 4) ? W0 : W1;
    int colBase = (bx & 3) * 128;         // within the selected weight matrix
    int outBase = bx * 128;               // within 1024-wide P
    int rowBase = blockIdx.y * 128;
    int row = tid >> 2, kq = (tid & 3) << 2;
    int kr = tid >> 5, nq = (tid & 31) << 2;
    int niter = Kd >> 4;

    float acc[2][8][4];
    #pragma unroll
    for (int mt = 0; mt < 2; mt++)
        #pragma unroll
        for (int nt = 0; nt < 8; nt++)
            #pragma unroll
            for (int i = 0; i < 4; i++) acc[mt][nt][i] = 0.f;

    auto do_load = [&](int iter, TileRegs& r) {
        int kk = iter << 4;
        r.a0 = ld4(A + (size_t)(rowBase + row)*Kd + kk + kq);
        r.a1 = ld4(A + (size_t)(rowBase + row + 64)*Kd + kk + kq);
        r.b0 = ld4(W + (size_t)(kk + kr)*HIDD + colBase + nq);
        r.b1 = ld4(W + (size_t)(kk + kr + 8)*HIDD + colBase + nq);
    };

    TileRegs r;
    do_load(0, r);
    s_store(As[0], Bs[0], tid, r);
    __syncthreads();

    int buf = 0;
    for (int iter = 0; iter < niter; ++iter) {
        if (iter + 1 < niter) do_load(iter + 1, r);
        mma_tile(As[buf], Bs[buf], wm, wn, lane, acc);
        if (iter + 1 < niter) {
            s_store(As[buf ^ 1], Bs[buf ^ 1], tid, r);
            __syncthreads();
            buf ^= 1;
        }
    }

    int grp = lane >> 2, tig = lane & 3;
    #pragma unroll
    for (int mt = 0; mt < 2; mt++) {
        #pragma unroll
        for (int nt = 0; nt < 8; nt++) {
            int orow = rowBase + (wm << 5) + (mt << 4) + grp;
            int col = outBase + (wn << 6) + (nt << 3) + (tig << 1);
            float2 lo = make_float2(acc[mt][nt][0], acc[mt][nt][1]);
            float2 hi = make_float2(acc[mt][nt][2], acc[mt][nt][3]);
            *reinterpret_cast<float2*>(P + (size_t)orow*INDIM + col)     = lo;
            *reinterpret_cast<float2*>(P + (size_t)(orow+8)*INDIM + col) = hi;
        }
    }
}

// Post-GEMM graph combine: h[n,j] = wL*P[nL,j] + wU*P[nU,j] + P[n,512+j] + bias[j]
__global__ void k_combine(const float* __restrict__ P,
                          const float* __restrict__ alpha,
                          const float* __restrict__ bias,
                          float* __restrict__ h) {
    int idx = blockIdx.x*256 + threadIdx.x;   // over NN*128 float4s
    int n = idx >> 7, j4 = idx & 127;
    int b = n / HW, pos = n % HW, r = pos / 7, c = pos % 7;
    int nL = (c > 0) ? n - 1 : n;
    int nU = (r > 0) ? n - 7 : n;
    float wL = (c > 0) ? alpha[b*EPB + r*6 + (c-1)]      : 0.f;
    float wU = (r > 0) ? alpha[b*EPB + 42 + (r-1)*7 + c] : 0.f;
    int deg = (c > 0) + (r > 0);
    float inv = 1.f / (float)(deg > 0 ? deg : 1);
    wL *= inv; wU *= inv;
    const float4* P4 = reinterpret_cast<const float4*>(P);
    float4 pL = P4[(size_t)nL*256 + j4];
    float4 pU = P4[(size_t)nU*256 + j4];
    float4 pr = P4[(size_t)n*256 + 128 + j4];
    float4 bb = reinterpret_cast<const float4*>(bias)[j4];
    float4 o;
    o.x = wL*pL.x + wU*pU.x + pr.x + bb.x;
    o.y = wL*pL.y + wU*pU.y + pr.y + bb.y;
    o.z = wL*pL.z + wU*pU.z + pr.z + bb.z;
    o.w = wL*pL.w + wU*pU.w + pr.w + bb.w;
    reinterpret_cast<float4*>(h)[idx] = o;
}

// ---------------------------------------------------------------------------
// Decoder GEMM: Y = relu(X@W[0:512] + nodew*W[512] + bias)
__global__ __launch_bounds__(256)
void k_gemm_dec_tf32(const float* __restrict__ A, const float* __restrict__ W,
                     const float* __restrict__ nodew, const float* __restrict__ bias,
                     float* __restrict__ Y) {
    const int Kd = HIDD;
    __shared__ __align__(16) unsigned As[2][16][132];
    __shared__ __align__(16) unsigned Bs[2][16][132];
    int tid = threadIdx.x, lane = tid & 31, wid = tid >> 5;
    int wm = wid & 3, wn = wid >> 2;
    int rowBase = blockIdx.y * 128, colBase = blockIdx.x * 128;
    int row = tid >> 2, kq = (tid & 3) << 2;
    int kr = tid >> 5, nq = (tid & 31) << 2;
    int niter = Kd >> 4;

    float acc[2][8][4];
    #pragma unroll
    for (int mt = 0; mt < 2; mt++)
        #pragma unroll
        for (int nt = 0; nt < 8; nt++)
            #pragma unroll
            for (int i = 0; i < 4; i++) acc[mt][nt][i] = 0.f;

    auto do_load = [&](int iter, TileRegs& r) {
        int kk = iter << 4;
        r.a0 = ld4(A + (size_t)(rowBase + row)*Kd + kk + kq);
        r.a1 = ld4(A + (size_t)(rowBase + row + 64)*Kd + kk + kq);
        r.b0 = ld4(W + (size_t)(kk + kr)*HIDD + colBase + nq);
        r.b1 = ld4(W + (size_t)(kk + kr + 8)*HIDD + colBase + nq);
    };

    TileRegs r;
    do_load(0, r);
    s_store(As[0], Bs[0], tid, r);
    __syncthreads();

    int buf = 0;
    for (int iter = 0; iter < niter; ++iter) {
        if (iter + 1 < niter) do_load(iter + 1, r);
        mma_tile(As[buf], Bs[buf], wm, wn, lane, acc);
        if (iter + 1 < niter) {
            s_store(As[buf ^ 1], Bs[buf ^ 1], tid, r);
            __syncthreads();
            buf ^= 1;
        }
    }

    const float* wlast = W + (size_t)HIDD * HIDD;
    int grp = lane >> 2, tig = lane & 3;
    #pragma unroll
    for (int mt = 0; mt < 2; mt++) {
        #pragma unroll
        for (int nt = 0; nt < 8; nt++) {
            int orow = rowBase + (wm << 5) + (mt << 4) + grp;
            int col = colBase + (wn << 6) + (nt << 3) + (tig << 1);
            float nw0 = nodew[orow], nw1 = nodew[orow + 8];
            float w0 = wlast[col], w1 = wlast[col+1];
            float b0 = bias[col], b1 = bias[col+1];
            float2 lo = make_float2(fmaxf(acc[mt][nt][0] + nw0*w0 + b0, 0.f),
                                    fmaxf(acc[mt][nt][1] + nw0*w1 + b1, 0.f));
            float2 hi = make_float2(fmaxf(acc[mt][nt][2] + nw1*w0 + b0, 0.f),
                                    fmaxf(acc[mt][nt][3] + nw1*w1 + b1, 0.f));
            *reinterpret_cast<float2*>(Y + (size_t)orow*HIDD + col)     = lo;
            *reinterpret_cast<float2*>(Y + (size_t)(orow+8)*HIDD + col) = hi;
        }
    }
}

// ---------------------------------------------------------------------------
// BN stats: deterministic two-stage column sum/sumsq
__global__ void k_colstat(const float* __restrict__ h,
                          float* __restrict__ psum, float* __restrict__ psq) {
    int t = threadIdx.x;
    int blk = blockIdx.x;
    const int rows = NN / STAT_BLOCKS;
    int r0 = blk * rows;
    float s0 = 0.f, q0 = 0.f, s1 = 0.f, q1 = 0.f;
    for (int r = r0; r < r0 + rows; ++r) {
        float v0 = h[(size_t)r*HIDD + t];
        float v1 = h[(size_t)r*HIDD + 256 + t];
        s0 += v0; q0 += v0*v0; s1 += v1; q1 += v1*v1;
    }
    psum[blk*HIDD + t] = s0; psum[blk*HIDD + 256 + t] = s1;
    psq [blk*HIDD + t] = q0; psq [blk*HIDD + 256 + t] = q1;
}

__global__ void k_colfinish(const float* __restrict__ psum, const float* __restrict__ psq,
                            const float* __restrict__ gamma, const float* __restrict__ beta,
                            float* __restrict__ scale, float* __restrict__ shift) {
    int c = threadIdx.x;
    float s = 0.f, q = 0.f;
    for (int j = 0; j < STAT_BLOCKS; j++) { s += psum[j*HIDD + c]; q += psq[j*HIDD + c]; }
    float mean = s / (float)NN;
    float var  = q / (float)NN - mean*mean;
    float sc = gamma[c] * rsqrtf(var + 1e-5f);
    scale[c] = sc;
    shift[c] = beta[c] - mean*sc;
}

__global__ void k_bnrelu(float* __restrict__ h,
                         const float* __restrict__ scale, const float* __restrict__ shift) {
    int idx = blockIdx.x*256 + threadIdx.x;
    float4 v = reinterpret_cast<float4*>(h)[idx];
    int c = (idx & 127) << 2;
    v.x = fmaxf(fmaf(v.x, scale[c+0], shift[c+0]), 0.f);
    v.y = fmaxf(fmaf(v.y, scale[c+1], shift[c+1]), 0.f);
    v.z = fmaxf(fmaf(v.z, scale[c+2], shift[c+2]), 0.f);
    v.w = fmaxf(fmaf(v.w, scale[c+3], shift[c+3]), 0.f);
    reinterpret_cast<float4*>(h)[idx] = v;
}

// ---------------------------------------------------------------------------
// Output transpose: y[N,512] -> out[B,512,7,7]
__global__ void k_out(const float* __restrict__ y, float* __restrict__ out) {
    int b = blockIdx.x >> 2;
    int t = blockIdx.x & 3;
    __shared__ float tile[49*129];
    for (int i = threadIdx.x; i < 49*128; i += 256) {
        int pos = i >> 7, ch = i & 127;
        tile[pos*129 + ch] = y[((size_t)(b*HW + pos))*HIDD + t*128 + ch];
    }
    __syncthreads();
    for (int i = threadIdx.x; i < 49*128; i += 256) {
        int ch = i / 49, pos = i % 49;
        out[((size_t)(b*512) + t*128 + ch)*HW + pos] = tile[pos*129 + ch];
    }
}

// ---------------------------------------------------------------------------
extern "C" void kernel_launch(void* const* d_in, const int* in_sizes, int n_in,
                              void* d_out, int out_size) {
    const float* vis     = (const float*)d_in[0];
    const float* tac     = (const float*)d_in[1];
    const float* projW   = (const float*)d_in[2];
    const float* projb   = (const float*)d_in[3];
    const float* g1relW  = (const float*)d_in[4];
    const float* g1relb  = (const float*)d_in[5];
    const float* g1rootW = (const float*)d_in[6];
    const float* bn1g    = (const float*)d_in[7];
    const float* bn1b    = (const float*)d_in[8];
    const float* g2relW  = (const float*)d_in[9];
    const float* g2relb  = (const float*)d_in[10];
    const float* g2rootW = (const float*)d_in[11];
    const float* bn2g    = (const float*)d_in[12];
    const float* bn2b    = (const float*)d_in[13];
    const float* decW    = (const float*)d_in[14];
    const float* decb    = (const float*)d_in[15];
    float* out = (float*)d_out;

    float *node, *P, *h1, *h2, *cpart, *coords, *ea, *alpha, *nodew, *epart, *sumexp;
    float *psum, *psq, *scale, *shift;
    cudaGetSymbolAddress((void**)&node,   g_node);
    cudaGetSymbolAddress((void**)&P,      g_P);
    cudaGetSymbolAddress((void**)&h1,     g_h1);
    cudaGetSymbolAddress((void**)&h2,     g_h2);
    cudaGetSymbolAddress((void**)&cpart,  g_coords_part);
    cudaGetSymbolAddress((void**)&coords, g_coords);
    cudaGetSymbolAddress((void**)&ea,     g_ea);
    cudaGetSymbolAddress((void**)&alpha,  g_alpha);
    cudaGetSymbolAddress((void**)&nodew,  g_nodew);
    cudaGetSymbolAddress((void**)&epart,  g_epart);
    cudaGetSymbolAddress((void**)&sumexp, g_sumexp);
    cudaGetSymbolAddress((void**)&psum,   g_psum);
    cudaGetSymbolAddress((void**)&psq,    g_psq);
    cudaGetSymbolAddress((void**)&scale,  g_scale);
    cudaGetSymbolAddress((void**)&shift,  g_shift);

    dim3 gcat(8, NN/128);       // (8, 392) cat GEMM
    dim3 gdec(HIDD/128, NN/128);

    k_build_node<<<BATCH*8, 256>>>(vis, tac, projW, node, cpart);
    k_coords_fin<<<NN/256, 256>>>(cpart, projb, coords);
    k_edge<<<EDGE_BLOCKS, 256>>>(coords, ea, alpha, epart);
    k_sumexp<<<1, 512>>>(epart, sumexp);
    k_alpha<<<EDGE_BLOCKS, 256>>>(alpha, sumexp);
    k_nodew<<<NN/256, 256>>>(ea, nodew);

    // GC1: P = node @ [Wrel|Wroot]; h1 = agg(P_rel) + P_root + b
    k_gemm_cat<<<gcat, 256>>>(node, g1relW, g1rootW, P, INDIM);
    k_combine<<<NN*128/256, 256>>>(P, alpha, g1relb, h1);
    k_colstat<<<STAT_BLOCKS, 256>>>(h1, psum, psq);
    k_colfinish<<<1, 512>>>(psum, psq, bn1g, bn1b, scale, shift);
    k_bnrelu<<<NN*128/256, 256>>>(h1, scale, shift);

    // GC2
    k_gemm_cat<<<gcat, 256>>>(h1, g2relW, g2rootW, P, HIDD);
    k_combine<<<NN*128/256, 256>>>(P, alpha, g2relb, h2);
    k_colstat<<<STAT_BLOCKS, 256>>>(h2, psum, psq);
    k_colfinish<<<1, 512>>>(psum, psq, bn2g, bn2b, scale, shift);
    k_bnrelu<<<NN*128/256, 256>>>(h2, scale, shift);

    // Decoder (+rank-1 node_w term) -> reuse g_node as y buffer
    k_gemm_dec_tf32<<<gdec, 256>>>(h2, decW, nodew, decb, node);
    k_out<<<BATCH*4, 256>>>(node, out);
}

// round 7
// speedup vs baseline: 1.8637x; 1.1928x over previous
#include <cuda_runtime.h>
#include <math.h>

// Problem constants (fixed shapes)
#define BATCH 1024
#define HW 49
#define NN (BATCH*HW)        // 50176
#define INDIM 1024
#define HIDD 512
#define EPB 84
#define EE (BATCH*EPB)       // 86016
#define EDGE_BLOCKS 336
#define STAT_BLOCKS 512

// Scratch (static device globals; no allocations allowed)
__device__ float g_node[(size_t)NN*INDIM];   // tf32-rounded node feats; reused as decoder output
__device__ float g_P   [(size_t)NN*INDIM];   // cat-GEMM output [N, 1024] = [rel | root]
__device__ float g_h1  [(size_t)NN*HIDD];
__device__ float g_h2  [(size_t)NN*HIDD];
__device__ float g_wc  [1835520];            // tf32-rounded weights
__device__ float g_coords_part[(size_t)NN*16];
__device__ float g_coords[NN*2];
__device__ float g_ea  [EE];
__device__ float g_alpha[EE];
__device__ float g_nodew[NN];
__device__ float g_epart[EDGE_BLOCKS];
__device__ float g_sumexp[1];
__device__ float g_psum[STAT_BLOCKS*HIDD];
__device__ float g_psq [STAT_BLOCKS*HIDD];
__device__ float g_scale[HIDD];
__device__ float g_shift[HIDD];

// wc offsets (floats)
#define WC_G1REL  0
#define WC_G1ROOT 524288
#define WC_G2REL  1048576
#define WC_G2ROOT 1310720
#define WC_DEC    1572864

__device__ __forceinline__ unsigned f2tf(float f) {
    unsigned u; asm("cvt.rna.tf32.f32 %0, %1;" : "=r"(u) : "f"(f)); return u;
}
__device__ __forceinline__ float f2tff(float f) { return __uint_as_float(f2tf(f)); }

__device__ __forceinline__ void cp16(unsigned s, const void* g) {
    asm volatile("cp.async.cg.shared.global [%0], [%1], 16;" :: "r"(s), "l"(g));
}
__device__ __forceinline__ void cp_commit() {
    asm volatile("cp.async.commit_group;");
}
template<int N> __device__ __forceinline__ void cp_wait() {
    asm volatile("cp.async.wait_group %0;" :: "n"(N));
}

// ---------------------------------------------------------------------------
// Weight convert: out[i] = tf32(in[i])
__global__ void k_cvt(const float* __restrict__ in, float* __restrict__ o, int n) {
    int i = blockIdx.x*256 + threadIdx.x;
    if (i < n) o[i] = f2tff(in[i]);
}

// ---------------------------------------------------------------------------
// K1: NCHW concat -> [N,1024] row-major (tf32-rounded) + coords partial dots
__global__ void k_build_node(const float* __restrict__ vis,
                             const float* __restrict__ tac,
                             const float* __restrict__ pW,
                             float* __restrict__ node,
                             float* __restrict__ cpart) {
    int b = blockIdx.x >> 3;
    int t = blockIdx.x & 7;
    const float* src = (t < 4) ? vis : tac;
    __shared__ float tile[128*49];
    __shared__ float sW[256];
    const float* p = src + ((size_t)b*512 + (size_t)(t & 3)*128) * 49;
    for (int i = threadIdx.x; i < 128*49; i += 256) tile[i] = p[i];
    if (threadIdx.x < 256) sW[threadIdx.x] = pW[t*256 + threadIdx.x];
    __syncthreads();
    for (int i = threadIdx.x; i < 128*49; i += 256) {
        int pos = i >> 7, ch = i & 127;
        node[((size_t)(b*HW + pos))*INDIM + t*128 + ch] = f2tff(tile[ch*49 + pos]);
    }
    if (threadIdx.x < 98) {
        int pos = threadIdx.x >> 1, comp = threadIdx.x & 1;
        float s = 0.f;
        #pragma unroll 8
        for (int ch = 0; ch < 128; ch++)
            s += tile[ch*49 + pos] * sW[ch*2 + comp];
        cpart[((size_t)(b*HW + pos))*16 + t*2 + comp] = s;
    }
}

__global__ void k_coords_fin(const float* __restrict__ cpart,
                             const float* __restrict__ pb,
                             float* __restrict__ coords) {
    int n = blockIdx.x*256 + threadIdx.x;
    const float4* p = reinterpret_cast<const float4*>(cpart + (size_t)n*16);
    float4 a = p[0], b4 = p[1], c4 = p[2], d4 = p[3];
    float c0 = a.x + a.z + b4.x + b4.z + c4.x + c4.z + d4.x + d4.z;
    float c1 = a.y + a.w + b4.y + b4.w + c4.y + c4.w + d4.y + d4.w;
    coords[2*n]   = c0 + pb[0];
    coords[2*n+1] = c1 + pb[1];
}

// ---------------------------------------------------------------------------
// Edge pipeline (deterministic reductions)
__global__ void k_edge(const float* __restrict__ coords,
                       float* __restrict__ ea,
                       float* __restrict__ ex,
                       float* __restrict__ epart) {
    int e = blockIdx.x*256 + threadIdx.x;
    float v = 0.f;
    {
        int b = e / EPB, k = e % EPB;
        int s, d;
        if (k < 42) { int r = k/6, c = k%6; s = r*7+c; d = s+1; }
        else        { int k2 = k-42; int r = k2/7, c = k2%7; s = r*7+c; d = s+7; }
        s += b*HW; d += b*HW;
        float dx = coords[2*s]   - coords[2*d];
        float dy = coords[2*s+1] - coords[2*d+1];
        float dist = sqrtf(dx*dx + dy*dy);
        float a = 1.f / (1.f + expf(-(1.f/(dist + 1e-6f))));
        ea[e] = a;
        v = expf(a);
        ex[e] = v;
    }
    __shared__ float red[8];
    #pragma unroll
    for (int o = 16; o; o >>= 1) v += __shfl_down_sync(0xffffffffu, v, o);
    if ((threadIdx.x & 31) == 0) red[threadIdx.x >> 5] = v;
    __syncthreads();
    if (threadIdx.x < 8) {
        float s = red[threadIdx.x];
        #pragma unroll
        for (int o = 4; o; o >>= 1) s += __shfl_down_sync(0xffu, s, o);
        if (threadIdx.x == 0) epart[blockIdx.x] = s;
    }
}

__global__ void k_sumexp(const float* __restrict__ epart, float* __restrict__ out) {
    int t = threadIdx.x;
    float v = (t < EDGE_BLOCKS) ? epart[t] : 0.f;
    __shared__ float red[16];
    #pragma unroll
    for (int o = 16; o; o >>= 1) v += __shfl_down_sync(0xffffffffu, v, o);
    if ((t & 31) == 0) red[t >> 5] = v;
    __syncthreads();
    if (t < 16) {
        float s = red[t];
        #pragma unroll
        for (int o = 8; o; o >>= 1) s += __shfl_down_sync(0xffffu, s, o);
        if (t == 0) out[0] = s;
    }
}

__global__ void k_alpha(float* __restrict__ ex, const float* __restrict__ sumexp) {
    int e = blockIdx.x*256 + threadIdx.x;
    float inv = 1.f / (sumexp[0] + 1e-8f);
    ex[e] = ex[e] * inv;
}

__global__ void k_nodew(const float* __restrict__ ea, float* __restrict__ nw) {
    int n = blockIdx.x*256 + threadIdx.x;
    int b = n / HW, pos = n % HW, r = pos / 7, c = pos % 7;
    const float* base = ea + b*EPB;
    float s = 0.f; int cnt = 0;
    if (c > 0) { s += base[r*6 + (c-1)];     cnt++; }
    if (c < 6) { s += base[r*6 + c];         cnt++; }
    if (r > 0) { s += base[42 + (r-1)*7 + c]; cnt++; }
    if (r < 6) { s += base[42 + r*7 + c];     cnt++; }
    nw[n] = s / (float)cnt;
}

// ---------------------------------------------------------------------------
// cp.async 3-stage TF32 mma GEMM. 128x128 tile, BK=16, 8 warps 4Mx2N.
// A in smem row-major [128][20] (pad 4, conflict-free), B [16][132].
// Inputs must already be tf32-rounded (bit pattern in fp32).
#define MMA_TF32(d, a, b0v, b1v) \
    asm volatile("mma.sync.aligned.m16n8k8.row.col.f32.tf32.tf32.f32 " \
                 "{%0,%1,%2,%3}, {%4,%5,%6,%7}, {%8,%9}, {%0,%1,%2,%3};" \
                 : "+f"(d[0]), "+f"(d[1]), "+f"(d[2]), "+f"(d[3]) \
                 : "r"(a[0]), "r"(a[1]), "r"(a[2]), "r"(a[3]), "r"(b0v), "r"(b1v))

__device__ __forceinline__ void mma_tile(const float (*As)[20], const float (*Bs)[132],
                                         int wm, int wn, int lane, float acc[2][8][4]) {
    int grp = lane >> 2, tig = lane & 3;
    #pragma unroll
    for (int ks = 0; ks < 16; ks += 8) {
        unsigned ua[2][4];
        #pragma unroll
        for (int mt = 0; mt < 2; mt++) {
            int m = (wm << 5) + (mt << 4) + grp;
            ua[mt][0] = __float_as_uint(As[m][ks + tig]);
            ua[mt][1] = __float_as_uint(As[m + 8][ks + tig]);
            ua[mt][2] = __float_as_uint(As[m][ks + tig + 4]);
            ua[mt][3] = __float_as_uint(As[m + 8][ks + tig + 4]);
        }
        #pragma unroll
        for (int nt = 0; nt < 8; nt++) {
            int n = (wn << 6) + (nt << 3) + grp;
            unsigned b0 = __float_as_uint(Bs[ks + tig][n]);
            unsigned b1 = __float_as_uint(Bs[ks + tig + 4][n]);
            MMA_TF32(acc[0][nt], ua[0], b0, b1);
            MMA_TF32(acc[1][nt], ua[1], b0, b1);
        }
    }
}

#define A_STAGE_BYTES 10240   // 128*20*4
#define B_STAGE_BYTES 8448    // 16*132*4

// Concatenated GEMM: P[:,0:512] = A@W0, P[:,512:1024] = A@W1 (tf32 inputs)
__global__ __launch_bounds__(256)
void k_gemm_cat(const float* __restrict__ A, const float* __restrict__ W0,
                const float* __restrict__ W1, float* __restrict__ P, int Kd) {
    __shared__ __align__(16) float As[3][128][20];
    __shared__ __align__(16) float Bs[3][16][132];
    int tid = threadIdx.x, lane = tid & 31, wid = tid >> 5;
    int wm = wid & 3, wn = wid >> 2;
    int bx = blockIdx.x;
    const float* W = (bx < 4) ? W0 : W1;
    int colBase = (bx & 3) * 128;
    int outBase = bx * 128;
    int rowBase = blockIdx.y * 128;
    int niter = Kd >> 4;

    // cp.async mapping
    int ar = tid >> 2, akc = (tid & 3) << 2;      // A: rows ar, ar+64; 4 floats at akc
    int bkr = tid >> 5, bnc = (tid & 31) << 2;    // B: k-rows bkr, bkr+8
    unsigned sA = (unsigned)__cvta_generic_to_shared(&As[0][0][0]);
    unsigned sB = (unsigned)__cvta_generic_to_shared(&Bs[0][0][0]);

    float acc[2][8][4];
    #pragma unroll
    for (int mt = 0; mt < 2; mt++)
        #pragma unroll
        for (int nt = 0; nt < 8; nt++)
            #pragma unroll
            for (int i = 0; i < 4; i++) acc[mt][nt][i] = 0.f;

    auto load_stage = [&](int st, int kk) {
        const float* a0 = A + (size_t)(rowBase + ar)*Kd + kk + akc;
        cp16(sA + st*A_STAGE_BYTES + ar*80 + akc*4, a0);
        cp16(sA + st*A_STAGE_BYTES + (ar+64)*80 + akc*4, a0 + (size_t)64*Kd);
        const float* b0 = W + (size_t)(kk + bkr)*HIDD + colBase + bnc;
        cp16(sB + st*B_STAGE_BYTES + bkr*528 + bnc*4, b0);
        cp16(sB + st*B_STAGE_BYTES + (bkr+8)*528 + bnc*4, b0 + (size_t)8*HIDD);
    };

    load_stage(0, 0);  cp_commit();
    load_stage(1, 16); cp_commit();

    int rd = 0, wr = 2;
    for (int iter = 0; iter < niter; ++iter) {
        cp_wait<1>();
        __syncthreads();
        mma_tile(As[rd], Bs[rd], wm, wn, lane, acc);
        if (iter + 2 < niter) load_stage(wr, (iter + 2) << 4);
        cp_commit();
        rd = (rd + 1) % 3; wr = (wr + 1) % 3;
    }

    int grp = lane >> 2, tig = lane & 3;
    #pragma unroll
    for (int mt = 0; mt < 2; mt++) {
        #pragma unroll
        for (int nt = 0; nt < 8; nt++) {
            int orow = rowBase + (wm << 5) + (mt << 4) + grp;
            int col = outBase + (wn << 6) + (nt << 3) + (tig << 1);
            *reinterpret_cast<float2*>(P + (size_t)orow*INDIM + col) =
                make_float2(acc[mt][nt][0], acc[mt][nt][1]);
            *reinterpret_cast<float2*>(P + (size_t)(orow+8)*INDIM + col) =
                make_float2(acc[mt][nt][2], acc[mt][nt][3]);
        }
    }
}

// Decoder: Y = relu(A@W + nodew*wlast + bias). A, W tf32-rounded; wlast raw.
__global__ __launch_bounds__(256)
void k_gemm_dec(const float* __restrict__ A, const float* __restrict__ W,
                const float* __restrict__ wlast, const float* __restrict__ nodew,
                const float* __restrict__ bias, float* __restrict__ Y) {
    const int Kd = HIDD;
    __shared__ __align__(16) float As[3][128][20];
    __shared__ __align__(16) float Bs[3][16][132];
    int tid = threadIdx.x, lane = tid & 31, wid = tid >> 5;
    int wm = wid & 3, wn = wid >> 2;
    int colBase = blockIdx.x * 128;
    int rowBase = blockIdx.y * 128;
    int niter = Kd >> 4;

    int ar = tid >> 2, akc = (tid & 3) << 2;
    int bkr = tid >> 5, bnc = (tid & 31) << 2;
    unsigned sA = (unsigned)__cvta_generic_to_shared(&As[0][0][0]);
    unsigned sB = (unsigned)__cvta_generic_to_shared(&Bs[0][0][0]);

    float acc[2][8][4];
    #pragma unroll
    for (int mt = 0; mt < 2; mt++)
        #pragma unroll
        for (int nt = 0; nt < 8; nt++)
            #pragma unroll
            for (int i = 0; i < 4; i++) acc[mt][nt][i] = 0.f;

    auto load_stage = [&](int st, int kk) {
        const float* a0 = A + (size_t)(rowBase + ar)*Kd + kk + akc;
        cp16(sA + st*A_STAGE_BYTES + ar*80 + akc*4, a0);
        cp16(sA + st*A_STAGE_BYTES + (ar+64)*80 + akc*4, a0 + (size_t)64*Kd);
        const float* b0 = W + (size_t)(kk + bkr)*HIDD + colBase + bnc;
        cp16(sB + st*B_STAGE_BYTES + bkr*528 + bnc*4, b0);
        cp16(sB + st*B_STAGE_BYTES + (bkr+8)*528 + bnc*4, b0 + (size_t)8*HIDD);
    };

    load_stage(0, 0);  cp_commit();
    load_stage(1, 16); cp_commit();

    int rd = 0, wr = 2;
    for (int iter = 0; iter < niter; ++iter) {
        cp_wait<1>();
        __syncthreads();
        mma_tile(As[rd], Bs[rd], wm, wn, lane, acc);
        if (iter + 2 < niter) load_stage(wr, (iter + 2) << 4);
        cp_commit();
        rd = (rd + 1) % 3; wr = (wr + 1) % 3;
    }

    int grp = lane >> 2, tig = lane & 3;
    #pragma unroll
    for (int mt = 0; mt < 2; mt++) {
        #pragma unroll
        for (int nt = 0; nt < 8; nt++) {
            int orow = rowBase + (wm << 5) + (mt << 4) + grp;
            int col = colBase + (wn << 6) + (nt << 3) + (tig << 1);
            float nw0 = nodew[orow], nw1 = nodew[orow + 8];
            float w0 = wlast[col], w1 = wlast[col+1];
            float b0 = bias[col], b1 = bias[col+1];
            *reinterpret_cast<float2*>(Y + (size_t)orow*HIDD + col) =
                make_float2(fmaxf(acc[mt][nt][0] + nw0*w0 + b0, 0.f),
                            fmaxf(acc[mt][nt][1] + nw0*w1 + b1, 0.f));
            *reinterpret_cast<float2*>(Y + (size_t)(orow+8)*HIDD + col) =
                make_float2(fmaxf(acc[mt][nt][2] + nw1*w0 + b0, 0.f),
                            fmaxf(acc[mt][nt][3] + nw1*w1 + b1, 0.f));
        }
    }
}

// ---------------------------------------------------------------------------
// Fused combine + column stats:
// h[n,j] = wL*P[nL,j] + wU*P[nU,j] + P[n,512+j] + bias[j]; per-block col partials.
__global__ void k_combine_stat(const float* __restrict__ P,
                               const float* __restrict__ alpha,
                               const float* __restrict__ bias,
                               float* __restrict__ h,
                               float* __restrict__ psum, float* __restrict__ psq) {
    int t = threadIdx.x;           // 256; cols 2t, 2t+1
    int blk = blockIdx.x;          // 512 blocks x 98 rows
    int c0 = t << 1;
    float b0 = bias[c0], b1 = bias[c0+1];
    float s0 = 0.f, q0 = 0.f, s1 = 0.f, q1 = 0.f;
    int r0 = blk * (NN / STAT_BLOCKS);
    const float2* P2 = reinterpret_cast<const float2*>(P);
    float2* h2 = reinterpret_cast<float2*>(h);
    for (int r = 0; r < NN / STAT_BLOCKS; ++r) {
        int n = r0 + r;
        int b = n / HW, pos = n % HW, rr = pos / 7, cc = pos % 7;
        int nL = (cc > 0) ? n - 1 : n;
        int nU = (rr > 0) ? n - 7 : n;
        float wL = (cc > 0) ? alpha[b*EPB + rr*6 + (cc-1)]      : 0.f;
        float wU = (rr > 0) ? alpha[b*EPB + 42 + (rr-1)*7 + cc] : 0.f;
        int deg = (cc > 0) + (rr > 0);
        float inv = 1.f / (float)(deg > 0 ? deg : 1);
        wL *= inv; wU *= inv;
        float2 pL = P2[(size_t)nL*512 + t];
        float2 pU = P2[(size_t)nU*512 + t];
        float2 pr = P2[(size_t)n*512 + 256 + t];
        float ox = wL*pL.x + wU*pU.x + pr.x + b0;
        float oy = wL*pL.y + wU*pU.y + pr.y + b1;
        h2[(size_t)n*256 + t] = make_float2(ox, oy);
        s0 += ox; q0 += ox*ox; s1 += oy; q1 += oy*oy;
    }
    psum[blk*HIDD + c0] = s0; psum[blk*HIDD + c0+1] = s1;
    psq [blk*HIDD + c0] = q0; psq [blk*HIDD + c0+1] = q1;
}

__global__ void k_colfinish(const float* __restrict__ psum, const float* __restrict__ psq,
                            const float* __restrict__ gamma, const float* __restrict__ beta,
                            float* __restrict__ scale, float* __restrict__ shift) {
    int c = threadIdx.x;
    float s = 0.f, q = 0.f;
    for (int j = 0; j < STAT_BLOCKS; j++) { s += psum[j*HIDD + c]; q += psq[j*HIDD + c]; }
    float mean = s / (float)NN;
    float var  = q / (float)NN - mean*mean;
    float sc = gamma[c] * rsqrtf(var + 1e-5f);
    scale[c] = sc;
    shift[c] = beta[c] - mean*sc;
}

// BN + relu + tf32-round (output feeds next GEMM's A)
__global__ void k_bnrelu(float* __restrict__ h,
                         const float* __restrict__ scale, const float* __restrict__ shift) {
    int idx = blockIdx.x*256 + threadIdx.x;
    float4 v = reinterpret_cast<float4*>(h)[idx];
    int c = (idx & 127) << 2;
    v.x = f2tff(fmaxf(fmaf(v.x, scale[c+0], shift[c+0]), 0.f));
    v.y = f2tff(fmaxf(fmaf(v.y, scale[c+1], shift[c+1]), 0.f));
    v.z = f2tff(fmaxf(fmaf(v.z, scale[c+2], shift[c+2]), 0.f));
    v.w = f2tff(fmaxf(fmaf(v.w, scale[c+3], shift[c+3]), 0.f));
    reinterpret_cast<float4*>(h)[idx] = v;
}

// ---------------------------------------------------------------------------
// Output transpose: y[N,512] -> out[B,512,7,7]
__global__ void k_out(const float* __restrict__ y, float* __restrict__ out) {
    int b = blockIdx.x >> 2;
    int t = blockIdx.x & 3;
    __shared__ float tile[49*129];
    for (int i = threadIdx.x; i < 49*128; i += 256) {
        int pos = i >> 7, ch = i & 127;
        tile[pos*129 + ch] = y[((size_t)(b*HW + pos))*HIDD + t*128 + ch];
    }
    __syncthreads();
    for (int i = threadIdx.x; i < 49*128; i += 256) {
        int ch = i / 49, pos = i % 49;
        out[((size_t)(b*512) + t*128 + ch)*HW + pos] = tile[pos*129 + ch];
    }
}

// ---------------------------------------------------------------------------
extern "C" void kernel_launch(void* const* d_in, const int* in_sizes, int n_in,
                              void* d_out, int out_size) {
    const float* vis     = (const float*)d_in[0];
    const float* tac     = (const float*)d_in[1];
    const float* projW   = (const float*)d_in[2];
    const float* projb   = (const float*)d_in[3];
    const float* g1relW  = (const float*)d_in[4];
    const float* g1relb  = (const float*)d_in[5];
    const float* g1rootW = (const float*)d_in[6];
    const float* bn1g    = (const float*)d_in[7];
    const float* bn1b    = (const float*)d_in[8];
    const float* g2relW  = (const float*)d_in[9];
    const float* g2relb  = (const float*)d_in[10];
    const float* g2rootW = (const float*)d_in[11];
    const float* bn2g    = (const float*)d_in[12];
    const float* bn2b    = (const float*)d_in[13];
    const float* decW    = (const float*)d_in[14];
    const float* decb    = (const float*)d_in[15];
    float* out = (float*)d_out;

    float *node, *P, *h1, *h2, *wc, *cpart, *coords, *ea, *alpha, *nodew, *epart, *sumexp;
    float *psum, *psq, *scale, *shift;
    cudaGetSymbolAddress((void**)&node,   g_node);
    cudaGetSymbolAddress((void**)&P,      g_P);
    cudaGetSymbolAddress((void**)&h1,     g_h1);
    cudaGetSymbolAddress((void**)&h2,     g_h2);
    cudaGetSymbolAddress((void**)&wc,     g_wc);
    cudaGetSymbolAddress((void**)&cpart,  g_coords_part);
    cudaGetSymbolAddress((void**)&coords, g_coords);
    cudaGetSymbolAddress((void**)&ea,     g_ea);
    cudaGetSymbolAddress((void**)&alpha,  g_alpha);
    cudaGetSymbolAddress((void**)&nodew,  g_nodew);
    cudaGetSymbolAddress((void**)&epart,  g_epart);
    cudaGetSymbolAddress((void**)&sumexp, g_sumexp);
    cudaGetSymbolAddress((void**)&psum,   g_psum);
    cudaGetSymbolAddress((void**)&psq,    g_psq);
    cudaGetSymbolAddress((void**)&scale,  g_scale);
    cudaGetSymbolAddress((void**)&shift,  g_shift);

    dim3 gcat(8, NN/128);        // (8, 392)
    dim3 gdec(HIDD/128, NN/128); // (4, 392)

    // Weight tf32 conversion (tiny)
    k_cvt<<<2048, 256>>>(g1relW,  wc + WC_G1REL,  INDIM*HIDD);
    k_cvt<<<2048, 256>>>(g1rootW, wc + WC_G1ROOT, INDIM*HIDD);
    k_cvt<<<1024, 256>>>(g2relW,  wc + WC_G2REL,  HIDD*HIDD);
    k_cvt<<<1024, 256>>>(g2rootW, wc + WC_G2ROOT, HIDD*HIDD);
    k_cvt<<<1024, 256>>>(decW,    wc + WC_DEC,    HIDD*HIDD);

    k_build_node<<<BATCH*8, 256>>>(vis, tac, projW, node, cpart);
    k_coords_fin<<<NN/256, 256>>>(cpart, projb, coords);
    k_edge<<<EDGE_BLOCKS, 256>>>(coords, ea, alpha, epart);
    k_sumexp<<<1, 512>>>(epart, sumexp);
    k_alpha<<<EDGE_BLOCKS, 256>>>(alpha, sumexp);
    k_nodew<<<NN/256, 256>>>(ea, nodew);

    // GC1
    k_gemm_cat<<<gcat, 256>>>(node, wc + WC_G1REL, wc + WC_G1ROOT, P, INDIM);
    k_combine_stat<<<STAT_BLOCKS, 256>>>(P, alpha, g1relb, h1, psum, psq);
    k_colfinish<<<1, 512>>>(psum, psq, bn1g, bn1b, scale, shift);
    k_bnrelu<<<NN*128/256, 256>>>(h1, scale, shift);

    // GC2
    k_gemm_cat<<<gcat, 256>>>(h1, wc + WC_G2REL, wc + WC_G2ROOT, P, HIDD);
    k_combine_stat<<<STAT_BLOCKS, 256>>>(P, alpha, g2relb, h2, psum, psq);
    k_colfinish<<<1, 512>>>(psum, psq, bn2g, bn2b, scale, shift);
    k_bnrelu<<<NN*128/256, 256>>>(h2, scale, shift);

    // Decoder (+rank-1 node_w via raw last row of decW) -> reuse g_node
    k_gemm_dec<<<gdec, 256>>>(h2, wc + WC_DEC, decW + (size_t)HIDD*HIDD, nodew, decb, node);
    k_out<<<BATCH*4, 256>>>(node, out);
}